// round 15
// baseline (speedup 1.0000x reference)
#include <cuda_runtime.h>
#include <cuda_bf16.h>
#include <math.h>
#include <cstdint>

#define BB 4
#define LL 2048
#define DDM 1024
#define HH 16
#define NT (BB*LL)   // 8192 tokens

// ---------------- scratch (device globals: allocation-free rule) ----------------
__device__ float          g_qkv[(size_t)NT * 3 * DDM];      // q,k fp32 (v region unused)
__device__ __nv_bfloat16  g_x_hi[(size_t)NT * DDM];
__device__ __nv_bfloat16  g_x_lo[(size_t)NT * DDM];
__device__ __nv_bfloat16  g_ctx_hi[(size_t)NT * DDM];
__device__ __nv_bfloat16  g_ctx_lo[(size_t)NT * DDM];
__device__ __nv_bfloat16  g_wqkv_hi[(size_t)3 * DDM * DDM];
__device__ __nv_bfloat16  g_wqkv_lo[(size_t)3 * DDM * DDM];
__device__ __nv_bfloat16  g_wout_hi[(size_t)DDM * DDM];
__device__ __nv_bfloat16  g_wout_lo[(size_t)DDM * DDM];
__device__ __nv_bfloat16  g_q_hi[(size_t)NT * 64 * HH];
__device__ __nv_bfloat16  g_q_lo[(size_t)NT * 64 * HH];
__device__ __nv_bfloat16  g_k_hi[(size_t)NT * 64 * HH];
__device__ __nv_bfloat16  g_k_lo[(size_t)NT * 64 * HH];
__device__ __nv_bfloat16  g_vT_hi[(size_t)NT * 64 * HH];
__device__ __nv_bfloat16  g_vT_lo[(size_t)NT * 64 * HH];
__device__ float g_cs[LL * 32];
__device__ float g_sn[LL * 32];
__device__ int   g_sid[NT];

// ---------------- streams/events created BEFORE harness checkpoints (static ctor) ----------------
struct GraphStreams {
    cudaStream_t s1 = nullptr, s2 = nullptr;
    cudaEvent_t e0 = nullptr, e1 = nullptr, e2 = nullptr, e3 = nullptr;
    cudaEvent_t ea[BB] = {}, ef = nullptr;
    GraphStreams() {
        cudaStreamCreateWithFlags(&s1, cudaStreamNonBlocking);
        cudaStreamCreateWithFlags(&s2, cudaStreamNonBlocking);
        cudaEventCreateWithFlags(&e0, cudaEventDisableTiming);
        cudaEventCreateWithFlags(&e1, cudaEventDisableTiming);
        cudaEventCreateWithFlags(&e2, cudaEventDisableTiming);
        cudaEventCreateWithFlags(&e3, cudaEventDisableTiming);
        for (int i = 0; i < BB; i++) cudaEventCreateWithFlags(&ea[i], cudaEventDisableTiming);
        cudaEventCreateWithFlags(&ef, cudaEventDisableTiming);
    }
};
static GraphStreams g_gs;

// ---------------- fused: sequence_id normalize + rope tables ----------------
__global__ void prep_misc_kernel(const void* __restrict__ seqraw) {
    int idx = blockIdx.x * blockDim.x + threadIdx.x;
    if (idx < NT) {
        const int* w = (const int*)seqraw;
        bool is64 = (w[2*1000+1] == 0) && (w[2*1500+1] == 0) && (w[2*2047+1] == 0);
        g_sid[idx] = is64 ? w[2*idx] : w[idx];
    }
    if (idx < LL * 32) {
        int s = idx >> 5, i = idx & 31;
        double ang = (double)s * pow(10000.0, -(double)i / 32.0);
        g_cs[idx] = (float)cos(ang);
        g_sn[idx] = (float)sin(ang);
    }
}

// ---------------- helpers ----------------
__device__ __forceinline__ uint32_t bf16pack(float a, float b) {
    __nv_bfloat16 ha = __float2bfloat16(a), hb = __float2bfloat16(b);
    uint32_t r = ((uint32_t)*(uint16_t*)&hb << 16) | (uint32_t)*(uint16_t*)&ha;
    return r;
}
__device__ __forceinline__ void mma_bf16(float* d, const uint32_t* a, const uint32_t* b) {
    asm volatile(
        "mma.sync.aligned.m16n8k16.row.col.f32.bf16.bf16.f32 "
        "{%0,%1,%2,%3}, {%4,%5,%6,%7}, {%8,%9}, {%0,%1,%2,%3};"
        : "+f"(d[0]), "+f"(d[1]), "+f"(d[2]), "+f"(d[3])
        : "r"(a[0]), "r"(a[1]), "r"(a[2]), "r"(a[3]), "r"(b[0]), "r"(b[1]));
}
__device__ __forceinline__ void ldsm4(uint32_t* r, uint32_t a) {
    asm volatile("ldmatrix.sync.aligned.m8n8.x4.shared.b16 {%0,%1,%2,%3}, [%4];"
        : "=r"(r[0]), "=r"(r[1]), "=r"(r[2]), "=r"(r[3]) : "r"(a));
}
__device__ __forceinline__ void ldsm2(uint32_t* r, uint32_t a) {
    asm volatile("ldmatrix.sync.aligned.m8n8.x2.shared.b16 {%0,%1}, [%2];"
        : "=r"(r[0]), "=r"(r[1]) : "r"(a));
}
__device__ __forceinline__ uint32_t smem_u32(const void* p) {
    uint32_t a;
    asm("{ .reg .u64 t; cvta.to.shared.u64 t, %1; cvt.u32.u64 %0, t; }" : "=r"(a) : "l"(p));
    return a;
}
__device__ __forceinline__ void cp16(uint32_t dst, const void* src) {
    asm volatile("cp.async.cg.shared.global [%0], [%1], 16;" :: "r"(dst), "l"(src));
}
__device__ __forceinline__ void cp_commit() {
    asm volatile("cp.async.commit_group;" ::: "memory");
}
template<int N>
__device__ __forceinline__ void cp_wait() {
    asm volatile("cp.async.wait_group %0;" :: "n"(N) : "memory");
}

// ---------------- weight prep: transpose [K][N] -> [N][K] + bf16 split ----------------
__global__ void __launch_bounds__(256) wprep_kernel(
    const float* __restrict__ w, __nv_bfloat16* __restrict__ thi,
    __nv_bfloat16* __restrict__ tlo, int N) {
    __shared__ float t[32][33];
    int n0 = blockIdx.x * 32, k0 = blockIdx.y * 32;
    int tx = threadIdx.x & 31, ty = threadIdx.x >> 5;
#pragma unroll
    for (int i = 0; i < 4; i++)
        t[ty + 8*i][tx] = w[(size_t)(k0 + ty + 8*i) * N + n0 + tx];
    __syncthreads();
#pragma unroll
    for (int i = 0; i < 4; i++) {
        float v = t[tx][ty + 8*i];
        __nv_bfloat16 h = __float2bfloat16(v);
        __nv_bfloat16 l = __float2bfloat16(v - __bfloat162float(h));
        size_t o = (size_t)(n0 + ty + 8*i) * 1024 + k0 + tx;
        thi[o] = h; tlo[o] = l;
    }
}

// ---------------- input LayerNorm -> bf16 hi/lo split ----------------
__global__ void __launch_bounds__(256) ln_kernel(
    const float* __restrict__ x, const float* __restrict__ w, const float* __restrict__ b) {
    int row = blockIdx.x;
    int tid = threadIdx.x;
    float4 v = ((const float4*)(x + (size_t)row * DDM))[tid];
    float s  = v.x + v.y + v.z + v.w;
    float ss = v.x*v.x + v.y*v.y + v.z*v.z + v.w*v.w;
    __shared__ float rs[8], rss[8];
#pragma unroll
    for (int o = 16; o; o >>= 1) {
        s  += __shfl_xor_sync(0xffffffffu, s,  o);
        ss += __shfl_xor_sync(0xffffffffu, ss, o);
    }
    if ((tid & 31) == 0) { rs[tid >> 5] = s; rss[tid >> 5] = ss; }
    __syncthreads();
    if (tid == 0) {
        float a = 0.f, c = 0.f;
#pragma unroll
        for (int i = 0; i < 8; i++) { a += rs[i]; c += rss[i]; }
        rs[0] = a; rss[0] = c;
    }
    __syncthreads();
    float mean = rs[0] * (1.0f / DDM);
    float var  = rss[0] * (1.0f / DDM) - mean * mean;
    float rstd = rsqrtf(var + 1e-5f);
    float4 wv = ((const float4*)w)[tid];
    float4 bv = ((const float4*)b)[tid];
    float o[4];
    o[0] = (v.x - mean) * rstd * wv.x + bv.x;
    o[1] = (v.y - mean) * rstd * wv.y + bv.y;
    o[2] = (v.z - mean) * rstd * wv.z + bv.z;
    o[3] = (v.w - mean) * rstd * wv.w + bv.w;
    size_t base = (size_t)row * DDM + tid * 4;
    __nv_bfloat16 h[4], l[4];
#pragma unroll
    for (int j = 0; j < 4; j++) {
        h[j] = __float2bfloat16(o[j]);
        l[j] = __float2bfloat16(o[j] - __bfloat162float(h[j]));
    }
    *(uint2*)(g_x_hi + base) = *(uint2*)h;
    *(uint2*)(g_x_lo + base) = *(uint2*)l;
}

// ---------------- tensor GEMM: mma.sync + 2-stage cp.async; V blocks write vT bf16 ----------------
#define SPAD 20
#define ARRW (128 * SPAD)
#define STGW (4 * ARRW)
#define GEMM_SMEM_BYTES (2 * STGW * 4)   // 81920
#define TSPITCH 132
template<int NN, bool WV>
__global__ void __launch_bounds__(256) gemm_mma_kernel(
    const __nv_bfloat16* __restrict__ Ahi, const __nv_bfloat16* __restrict__ Alo,
    const __nv_bfloat16* __restrict__ Bhi, const __nv_bfloat16* __restrict__ Blo,
    float* __restrict__ C, int n_off, int m_off) {
    extern __shared__ uint32_t sw[];
    const uint32_t sb = smem_u32(sw);
    int tid = threadIdx.x, lane = tid & 31, wid = tid >> 5;
    int m0 = blockIdx.y * 128 + m_off, n0 = blockIdx.x * 128 + n_off;
    int wm = (wid & 1) * 64, wn = (wid >> 1) * 32;
    int g = lane >> 2, q = lane & 3;
    int lrow = tid >> 2, lu = tid & 3;
    int lr = lane & 7, sel = lane >> 3;

    uint32_t aoff[4], boff[4];
#pragma unroll
    for (int mf = 0; mf < 4; mf++)
        aoff[mf] = (uint32_t)((wm + mf * 16 + (sel & 1) * 8 + lr) * SPAD + (sel >> 1) * 4) * 4;
#pragma unroll
    for (int nf = 0; nf < 4; nf++)
        boff[nf] = (uint32_t)((wn + nf * 8 + lr) * SPAD + (sel & 1) * 4) * 4;

    float acc[4][4][4] = {};

    auto load_chunk = [&](int kc, int st) {
        uint32_t base = sb + (uint32_t)st * (STGW * 4);
#pragma unroll
        for (int h = 0; h < 2; h++) {
            int row = lrow + h * 64;
            uint32_t so = (uint32_t)(row * SPAD + lu * 4) * 4;
            size_t gA = (size_t)(m0 + row) * 1024 + kc * 32 + lu * 8;
            size_t gB = (size_t)(n0 + row) * 1024 + kc * 32 + lu * 8;
            cp16(base + 0 * ARRW * 4 + so, Ahi + gA);
            cp16(base + 1 * ARRW * 4 + so, Alo + gA);
            cp16(base + 2 * ARRW * 4 + so, Bhi + gB);
            cp16(base + 3 * ARRW * 4 + so, Blo + gB);
        }
    };

    load_chunk(0, 0);
    cp_commit();

    for (int kc = 0; kc < 32; kc++) {
        int st = kc & 1;
        if (kc < 31) { load_chunk(kc + 1, st ^ 1); cp_commit(); cp_wait<1>(); }
        else         { cp_wait<0>(); }
        __syncthreads();
        uint32_t stb = sb + (uint32_t)st * (STGW * 4);
        uint32_t bAh = stb, bAl = stb + ARRW * 4, bBh = stb + 2 * ARRW * 4, bBl = stb + 3 * ARRW * 4;
#pragma unroll
        for (int ks = 0; ks < 2; ks++) {
            uint32_t ko = ks * 32;
            uint32_t ah[4][4], al[4][4], bh[4][2], bl[4][2];
#pragma unroll
            for (int mf = 0; mf < 4; mf++) {
                ldsm4(ah[mf], bAh + aoff[mf] + ko);
                ldsm4(al[mf], bAl + aoff[mf] + ko);
            }
#pragma unroll
            for (int nf = 0; nf < 4; nf++) {
                ldsm2(bh[nf], bBh + boff[nf] + ko);
                ldsm2(bl[nf], bBl + boff[nf] + ko);
            }
#pragma unroll
            for (int mf = 0; mf < 4; mf++)
#pragma unroll
                for (int nf = 0; nf < 4; nf++) {
                    mma_bf16(acc[mf][nf], ah[mf], bh[nf]);
                    mma_bf16(acc[mf][nf], ah[mf], bl[nf]);
                    mma_bf16(acc[mf][nf], al[mf], bh[nf]);
                }
        }
        __syncthreads();
    }

    if (WV) {
        float* ts = (float*)sw;
#pragma unroll
        for (int mf = 0; mf < 4; mf++)
#pragma unroll
            for (int nf = 0; nf < 4; nf++)
#pragma unroll
                for (int e = 0; e < 4; e++) {
                    int r = wm + mf * 16 + g + (e >> 1) * 8;
                    int c = wn + nf * 8 + q * 2 + (e & 1);
                    ts[c * TSPITCH + r] = acc[mf][nf][e];
                }
        __syncthreads();
        int b = m0 >> 11, l0v = m0 & (LL - 1);
        int nbase = n0 - 2048;
#pragma unroll
        for (int r8 = 0; r8 < 16; r8++) {
            int row = wid * 16 + r8;
            int nglob = nbase + row;
            int h = nglob >> 6, dh = nglob & 63;
            size_t off = (((size_t)(b * HH + h)) * 64 + dh) * LL + l0v + lane * 4;
            float4 v = *(float4*)&ts[row * TSPITCH + lane * 4];
            __nv_bfloat16 hh[4], llo[4];
            float vv[4] = {v.x, v.y, v.z, v.w};
#pragma unroll
            for (int j = 0; j < 4; j++) {
                hh[j]  = __float2bfloat16(vv[j]);
                llo[j] = __float2bfloat16(vv[j] - __bfloat162float(hh[j]));
            }
            *(uint2*)(g_vT_hi + off) = *(uint2*)hh;
            *(uint2*)(g_vT_lo + off) = *(uint2*)llo;
        }
    } else {
#pragma unroll
        for (int mf = 0; mf < 4; mf++)
#pragma unroll
            for (int nf = 0; nf < 4; nf++) {
                int m = m0 + wm + mf * 16 + g;
                int n = n0 + wn + nf * 8 + q * 2;
                *(float2*)&C[(size_t)m * NN + n]       = make_float2(acc[mf][nf][0], acc[mf][nf][1]);
                *(float2*)&C[(size_t)(m + 8) * NN + n] = make_float2(acc[mf][nf][2], acc[mf][nf][3]);
            }
    }
}

// ---------------- QK LayerNorm + RoPE, q/k passes merged -> head-major bf16 hi/lo ----------------
__global__ void __launch_bounds__(256) qkln_rope_kernel(
    const float* __restrict__ qw, const float* __restrict__ kw) {
    int token = blockIdx.x;
    int tid = threadIdx.x;
    int b = token >> 11, l = token & (LL - 1);
    __shared__ float bufq[DDM], bufk[DDM];
    __shared__ float red[4][8];
    const float* rowq = g_qkv + (size_t)token * 3 * DDM;
    float4 vq = ((const float4*)rowq)[tid];
    float4 vk = ((const float4*)(rowq + DDM))[tid];
    float s0 = vq.x + vq.y + vq.z + vq.w;
    float s1 = vq.x*vq.x + vq.y*vq.y + vq.z*vq.z + vq.w*vq.w;
    float s2 = vk.x + vk.y + vk.z + vk.w;
    float s3 = vk.x*vk.x + vk.y*vk.y + vk.z*vk.z + vk.w*vk.w;
#pragma unroll
    for (int o = 16; o; o >>= 1) {
        s0 += __shfl_xor_sync(0xffffffffu, s0, o);
        s1 += __shfl_xor_sync(0xffffffffu, s1, o);
        s2 += __shfl_xor_sync(0xffffffffu, s2, o);
        s3 += __shfl_xor_sync(0xffffffffu, s3, o);
    }
    if ((tid & 31) == 0) {
        int w = tid >> 5;
        red[0][w] = s0; red[1][w] = s1; red[2][w] = s2; red[3][w] = s3;
    }
    __syncthreads();
    if (tid < 4) {
        float a = 0.f;
#pragma unroll
        for (int i = 0; i < 8; i++) a += red[tid][i];
        red[tid][0] = a;
    }
    __syncthreads();
    float meanq = red[0][0] * (1.0f / DDM);
    float rstdq = rsqrtf(red[1][0] * (1.0f / DDM) - meanq * meanq + 1e-5f);
    float meank = red[2][0] * (1.0f / DDM);
    float rstdk = rsqrtf(red[3][0] * (1.0f / DDM) - meank * meank + 1e-5f);
    float4 wq = ((const float4*)qw)[tid];
    float4 wk = ((const float4*)kw)[tid];
    int c0 = tid * 4;
    bufq[c0 + 0] = (vq.x - meanq) * rstdq * wq.x;
    bufq[c0 + 1] = (vq.y - meanq) * rstdq * wq.y;
    bufq[c0 + 2] = (vq.z - meanq) * rstdq * wq.z;
    bufq[c0 + 3] = (vq.w - meanq) * rstdq * wq.w;
    bufk[c0 + 0] = (vk.x - meank) * rstdk * wk.x;
    bufk[c0 + 1] = (vk.y - meank) * rstdk * wk.y;
    bufk[c0 + 2] = (vk.z - meank) * rstdk * wk.z;
    bufk[c0 + 3] = (vk.w - meank) * rstdk * wk.w;
    __syncthreads();
    __nv_bfloat16 qh[4], ql[4], kh[4], kl[4];
#pragma unroll
    for (int j = 0; j < 4; j++) {
        int c = c0 + j;
        int d = c & 63;
        int i2 = d & 31;
        float cs = g_cs[l * 32 + i2];
        float sn = g_sn[l * 32 + i2];
        float rq = (d < 32) ? -bufq[c + 32] : bufq[c - 32];
        float rk = (d < 32) ? -bufk[c + 32] : bufk[c - 32];
        float oq = bufq[c] * cs + rq * sn;
        float ok = bufk[c] * cs + rk * sn;
        qh[j] = __float2bfloat16(oq);
        ql[j] = __float2bfloat16(oq - __bfloat162float(qh[j]));
        kh[j] = __float2bfloat16(ok);
        kl[j] = __float2bfloat16(ok - __bfloat162float(kh[j]));
    }
    int h = c0 >> 6;
    size_t off = (((size_t)b * HH + h) * LL + l) * 64 + (c0 & 63);
    *(uint2*)(g_q_hi + off) = *(uint2*)qh;
    *(uint2*)(g_q_lo + off) = *(uint2*)ql;
    *(uint2*)(g_k_hi + off) = *(uint2*)kh;
    *(uint2*)(g_k_lo + off) = *(uint2*)kl;
}

// ---------------- tensorized flash attention, 64x64 tiles, active k-range, reg prefetch ----------------
#define APAD 36
struct AttnSmem {
    uint32_t Qh[64*APAD], Ql[64*APAD];
    uint32_t Kh[64*APAD], Kl[64*APAD];
    uint32_t Vh[64*APAD], Vl[64*APAD];   // V^T tiles: [dh][l]
    uint32_t Ph[64*APAD], Pl[64*APAD];
    float Ss[64][65];
    float mrow[64], lrow[64], alpha[64];
    int   sidq[64], sidk[64];
    int   ktlo, kthi;
};

__global__ void __launch_bounds__(256) attn_kernel(int bh_off) {
    extern __shared__ char smem_raw[];
    AttnSmem& sm = *(AttnSmem*)smem_raw;
    int tid = threadIdx.x, lane = tid & 31, wid = tid >> 5;
    int wm = (wid & 1) * 32, wn = (wid >> 1) * 16;
    int g = lane >> 2, q = lane & 3;
    int lr = lane & 7, sel = lane >> 3;
    int q0 = blockIdx.x * 64;
    int bh = blockIdx.y + bh_off;
    int b = bh >> 4;

    uint32_t aoffA[2], boffB[2];
#pragma unroll
    for (int mf = 0; mf < 2; mf++)
        aoffA[mf] = (uint32_t)((wm + mf * 16 + (sel & 1) * 8 + lr) * APAD + (sel >> 1) * 4) * 4;
#pragma unroll
    for (int nf = 0; nf < 2; nf++)
        boffB[nf] = (uint32_t)((wn + nf * 8 + lr) * APAD + (sel & 1) * 4) * 4;

    const uint32_t uQh = smem_u32(sm.Qh), uQl = smem_u32(sm.Ql);
    const uint32_t uKh = smem_u32(sm.Kh), uKl = smem_u32(sm.Kl);
    const uint32_t uVh = smem_u32(sm.Vh), uVl = smem_u32(sm.Vl);
    const uint32_t uPh = smem_u32(sm.Ph), uPl = smem_u32(sm.Pl);

    auto load_tile = [&](uint32_t* dst, const __nv_bfloat16* src, int rstride) {
#pragma unroll
        for (int i = 0; i < 2; i++) {
            int u = tid + i * 256;
            int row = u >> 3, wq = (u & 7) * 4;
            uint4 v = *(const uint4*)(src + (size_t)row * rstride + wq * 2);
            *(uint4*)&dst[row * APAD + wq] = v;
        }
    };

    uint4 pf[8];
    int sid_next = 0;
    auto prefetch = [&](int kt) {
        const __nv_bfloat16* s0 = g_k_hi  + ((size_t)bh * LL + kt * 64) * 64;
        const __nv_bfloat16* s1 = g_k_lo  + ((size_t)bh * LL + kt * 64) * 64;
        const __nv_bfloat16* s2 = g_vT_hi + (size_t)bh * 64 * LL + kt * 64;
        const __nv_bfloat16* s3 = g_vT_lo + (size_t)bh * 64 * LL + kt * 64;
#pragma unroll
        for (int i = 0; i < 2; i++) {
            int u = tid + i * 256;
            int row = u >> 3, wq = (u & 7) * 4;
            pf[0 * 2 + i] = *(const uint4*)(s0 + (size_t)row * 64 + wq * 2);
            pf[1 * 2 + i] = *(const uint4*)(s1 + (size_t)row * 64 + wq * 2);
            pf[2 * 2 + i] = *(const uint4*)(s2 + (size_t)row * LL + wq * 2);
            pf[3 * 2 + i] = *(const uint4*)(s3 + (size_t)row * LL + wq * 2);
        }
        if (tid < 64) sid_next = g_sid[b * LL + kt * 64 + tid];
    };
    auto commit = [&]() {
#pragma unroll
        for (int i = 0; i < 2; i++) {
            int u = tid + i * 256;
            int row = u >> 3, wq = (u & 7) * 4;
            *(uint4*)&sm.Kh[row * APAD + wq] = pf[0 * 2 + i];
            *(uint4*)&sm.Kl[row * APAD + wq] = pf[1 * 2 + i];
            *(uint4*)&sm.Vh[row * APAD + wq] = pf[2 * 2 + i];
            *(uint4*)&sm.Vl[row * APAD + wq] = pf[3 * 2 + i];
        }
        if (tid < 64) sm.sidk[tid] = sid_next;
    };

    load_tile(sm.Qh, g_q_hi + ((size_t)bh * LL + q0) * 64, 64);
    load_tile(sm.Ql, g_q_lo + ((size_t)bh * LL + q0) * 64, 64);
    if (tid < 64) {
        sm.sidq[tid] = g_sid[b * LL + q0 + tid];
        sm.mrow[tid] = -INFINITY;
        sm.lrow[tid] = 0.f;
    }
    __syncthreads();

    if (tid < 32) {
        int kmin = g_sid[b * LL + tid * 64];
        int kmax = g_sid[b * LL + tid * 64 + 63];
        bool act = (kmax >= sm.sidq[0]) && (kmin <= sm.sidq[63]);
        uint32_t m = __ballot_sync(0xffffffffu, act);
        if (tid == 0) { sm.ktlo = __ffs(m) - 1; sm.kthi = 31 - __clz(m); }
    }
    __syncthreads();
    int ktlo = sm.ktlo, kthi = sm.kthi;

    float O[2][2][4] = {};

    prefetch(ktlo);
    commit();
    __syncthreads();

    for (int kt = ktlo; kt <= kthi; kt++) {
        if (kt < kthi) prefetch(kt + 1);

        float sacc[2][2][4] = {};
#pragma unroll
        for (int ks = 0; ks < 4; ks++) {
            uint32_t ko = ks * 32;
            uint32_t aH[2][4], aL[2][4], bH[2][2], bL[2][2];
#pragma unroll
            for (int mf = 0; mf < 2; mf++) {
                ldsm4(aH[mf], uQh + aoffA[mf] + ko);
                ldsm4(aL[mf], uQl + aoffA[mf] + ko);
            }
#pragma unroll
            for (int nf = 0; nf < 2; nf++) {
                ldsm2(bH[nf], uKh + boffB[nf] + ko);
                ldsm2(bL[nf], uKl + boffB[nf] + ko);
            }
#pragma unroll
            for (int mf = 0; mf < 2; mf++)
#pragma unroll
                for (int nf = 0; nf < 2; nf++) {
                    mma_bf16(sacc[mf][nf], aH[mf], bH[nf]);
                    mma_bf16(sacc[mf][nf], aH[mf], bL[nf]);
                    mma_bf16(sacc[mf][nf], aL[mf], bH[nf]);
                }
        }
#pragma unroll
        for (int mf = 0; mf < 2; mf++)
#pragma unroll
            for (int nf = 0; nf < 2; nf++) {
                int r = wm + mf * 16 + g, c = wn + nf * 8 + 2 * q;
#pragma unroll
                for (int e = 0; e < 4; e++) {
                    int rr = r + (e >> 1) * 8, cc = c + (e & 1);
                    float sv = sacc[mf][nf][e] * 0.125f;
                    if (sm.sidq[rr] != sm.sidk[cc]) sv = -1e30f;
                    sm.Ss[rr][cc] = sv;
                }
            }
        __syncthreads();

        {
            int r = tid >> 2, sub = tid & 3;
            float mloc = -INFINITY;
#pragma unroll
            for (int c = sub * 16; c < sub * 16 + 16; c++)
                mloc = fmaxf(mloc, sm.Ss[r][c]);
            mloc = fmaxf(mloc, __shfl_xor_sync(0xffffffffu, mloc, 1));
            mloc = fmaxf(mloc, __shfl_xor_sync(0xffffffffu, mloc, 2));
            float mold = sm.mrow[r];
            float mnew = fmaxf(mold, mloc);
            float ls = 0.f;
#pragma unroll
            for (int w = sub * 8; w < sub * 8 + 8; w++) {
                float p0 = __expf(sm.Ss[r][2 * w]     - mnew);
                float p1 = __expf(sm.Ss[r][2 * w + 1] - mnew);
                ls += p0 + p1;
                float h0 = __bfloat162float(__float2bfloat16(p0));
                float h1 = __bfloat162float(__float2bfloat16(p1));
                sm.Ph[r * APAD + w] = bf16pack(h0, h1);
                sm.Pl[r * APAD + w] = bf16pack(p0 - h0, p1 - h1);
            }
            ls += __shfl_xor_sync(0xffffffffu, ls, 1);
            ls += __shfl_xor_sync(0xffffffffu, ls, 2);
            if (sub == 0) {
                float a = __expf(mold - mnew);
                sm.alpha[r] = a;
                sm.lrow[r] = sm.lrow[r] * a + ls;
                sm.mrow[r] = mnew;
            }
        }
        __syncthreads();

#pragma unroll
        for (int mf = 0; mf < 2; mf++) {
            float a0 = sm.alpha[wm + mf * 16 + g];
            float a1 = sm.alpha[wm + mf * 16 + g + 8];
#pragma unroll
            for (int nf = 0; nf < 2; nf++) {
                O[mf][nf][0] *= a0; O[mf][nf][1] *= a0;
                O[mf][nf][2] *= a1; O[mf][nf][3] *= a1;
            }
        }
#pragma unroll
        for (int ks = 0; ks < 4; ks++) {
            uint32_t ko = ks * 32;
            uint32_t aH[2][4], aL[2][4], bH[2][2], bL[2][2];
#pragma unroll
            for (int mf = 0; mf < 2; mf++) {
                ldsm4(aH[mf], uPh + aoffA[mf] + ko);
                ldsm4(aL[mf], uPl + aoffA[mf] + ko);
            }
#pragma unroll
            for (int nf = 0; nf < 2; nf++) {
                ldsm2(bH[nf], uVh + boffB[nf] + ko);
                ldsm2(bL[nf], uVl + boffB[nf] + ko);
            }
#pragma unroll
            for (int mf = 0; mf < 2; mf++)
#pragma unroll
                for (int nf = 0; nf < 2; nf++) {
                    mma_bf16(O[mf][nf], aH[mf], bH[nf]);
                    mma_bf16(O[mf][nf], aH[mf], bL[nf]);
                    mma_bf16(O[mf][nf], aL[mf], bH[nf]);
                }
        }
        __syncthreads();
        if (kt < kthi) {
            commit();
            __syncthreads();
        }
    }

    int h = bh & 15;
#pragma unroll
    for (int mf = 0; mf < 2; mf++)
#pragma unroll
        for (int nf = 0; nf < 2; nf++) {
            int r = wm + mf * 16 + g, c = wn + nf * 8 + 2 * q;
#pragma unroll
            for (int half = 0; half < 2; half++) {
                int rr = r + half * 8;
                float il = 1.0f / sm.lrow[rr];
                float o0 = O[mf][nf][half * 2 + 0] * il;
                float o1 = O[mf][nf][half * 2 + 1] * il;
                float h0 = __bfloat162float(__float2bfloat16(o0));
                float h1 = __bfloat162float(__float2bfloat16(o1));
                size_t off = ((size_t)(b * LL + q0 + rr)) * DDM + h * 64 + c;
                *(uint32_t*)(g_ctx_hi + off) = bf16pack(h0, h1);
                *(uint32_t*)(g_ctx_lo + off) = bf16pack(o0 - h0, o1 - h1);
            }
        }
}

// ---------------- launch: stream-forked graph, batch-pipelined attn/out-GEMM ----------------
extern "C" void kernel_launch(void* const* d_in, const int* in_sizes, int n_in,
                              void* d_out, int out_size) {
    (void)in_sizes; (void)n_in; (void)out_size;
    const float* x      = (const float*)d_in[0];
    const void*  seq    = d_in[1];
    const float* ln_w   = (const float*)d_in[2];
    const float* ln_b   = (const float*)d_in[3];
    const float* w_qkv  = (const float*)d_in[4];
    const float* q_ln_w = (const float*)d_in[5];
    const float* k_ln_w = (const float*)d_in[6];
    const float* w_out  = (const float*)d_in[7];
    float* out = (float*)d_out;

    float* p_qkv;
    __nv_bfloat16 *p_xh, *p_xl, *p_ch, *p_cl, *p_wqh, *p_wql, *p_woh, *p_wol;
    cudaGetSymbolAddress((void**)&p_qkv, g_qkv);
    cudaGetSymbolAddress((void**)&p_xh,  g_x_hi);
    cudaGetSymbolAddress((void**)&p_xl,  g_x_lo);
    cudaGetSymbolAddress((void**)&p_ch,  g_ctx_hi);
    cudaGetSymbolAddress((void**)&p_cl,  g_ctx_lo);
    cudaGetSymbolAddress((void**)&p_wqh, g_wqkv_hi);
    cudaGetSymbolAddress((void**)&p_wql, g_wqkv_lo);
    cudaGetSymbolAddress((void**)&p_woh, g_wout_hi);
    cudaGetSymbolAddress((void**)&p_wol, g_wout_lo);

    cudaFuncSetAttribute((const void*)gemm_mma_kernel<3 * DDM, false>,
                         cudaFuncAttributeMaxDynamicSharedMemorySize, GEMM_SMEM_BYTES);
    cudaFuncSetAttribute((const void*)gemm_mma_kernel<3 * DDM, true>,
                         cudaFuncAttributeMaxDynamicSharedMemorySize, GEMM_SMEM_BYTES);
    cudaFuncSetAttribute((const void*)gemm_mma_kernel<DDM, false>,
                         cudaFuncAttributeMaxDynamicSharedMemorySize, GEMM_SMEM_BYTES);
    int attn_smem = (int)sizeof(AttnSmem);
    cudaFuncSetAttribute(attn_kernel, cudaFuncAttributeMaxDynamicSharedMemorySize, attn_smem);

    // fork side stream for independent prologue work
    cudaEventRecord(g_gs.e0, 0);
    cudaStreamWaitEvent(g_gs.s1, g_gs.e0, 0);
    prep_misc_kernel<<<(LL * 32 + 255) / 256, 256, 0, g_gs.s1>>>(seq);
    wprep_kernel<<<dim3(DDM / 32, DDM / 32), 256, 0, g_gs.s1>>>(w_out, p_woh, p_wol, DDM);
    cudaEventRecord(g_gs.e1, g_gs.s1);

    // main: LN + qkv-weight prep
    ln_kernel<<<NT, 256>>>(x, ln_w, ln_b);
    wprep_kernel<<<dim3(3 * DDM / 32, DDM / 32), 256>>>(w_qkv, p_wqh, p_wql, 3 * DDM);
    cudaEventRecord(g_gs.e2, 0);

    // V-columns GEMM on side stream 2 (overlaps QK GEMM tail + qkln)
    cudaStreamWaitEvent(g_gs.s2, g_gs.e2, 0);
    gemm_mma_kernel<3 * DDM, true><<<dim3(8, 64), 256, GEMM_SMEM_BYTES, g_gs.s2>>>(
        p_xh, p_xl, p_wqh, p_wql, p_qkv, 2048, 0);
    cudaEventRecord(g_gs.e3, g_gs.s2);

    // QK-columns GEMM on main stream
    gemm_mma_kernel<3 * DDM, false><<<dim3(16, 64), 256, GEMM_SMEM_BYTES>>>(
        p_xh, p_xl, p_wqh, p_wql, p_qkv, 0, 0);

    // qkln needs rope tables (e1) + qk GEMM (stream order)
    cudaStreamWaitEvent(0, g_gs.e1, 0);
    qkln_rope_kernel<<<NT, 256>>>(q_ln_w, k_ln_w);

    // attention per batch on main stream; out-GEMM chunks pipelined on s2
    cudaStreamWaitEvent(0, g_gs.e3, 0);          // vT ready
    for (int b = 0; b < BB; b++) {
        attn_kernel<<<dim3(LL / 64, HH), 256, attn_smem>>>(b * HH);
        cudaEventRecord(g_gs.ea[b], 0);
        cudaStreamWaitEvent(g_gs.s2, g_gs.ea[b], 0);   // s2 already waited e1 (w_out prep) via V-GEMM chain? no — wait explicitly
        if (b == 0) cudaStreamWaitEvent(g_gs.s2, g_gs.e1, 0);  // w_out weights ready
        gemm_mma_kernel<DDM, false><<<dim3(DDM / 128, LL / 128), 256, GEMM_SMEM_BYTES, g_gs.s2>>>(
            p_ch, p_cl, p_woh, p_wol, out, 0, b * LL);
    }
    cudaEventRecord(g_gs.ef, g_gs.s2);
    cudaStreamWaitEvent(0, g_gs.ef, 0);          // join s2 back to origin stream
}

// round 16
// speedup vs baseline: 1.1029x; 1.1029x over previous
#include <cuda_runtime.h>
#include <cuda_bf16.h>
#include <math.h>
#include <cstdint>

#define BB 4
#define LL 2048
#define DDM 1024
#define HH 16
#define NT (BB*LL)   // 8192 tokens

// ---------------- scratch (device globals: allocation-free rule) ----------------
__device__ float          g_qkv[(size_t)NT * 3 * DDM];      // q,k fp32 (v region unused)
__device__ __nv_bfloat16  g_x_hi[(size_t)NT * DDM];
__device__ __nv_bfloat16  g_x_lo[(size_t)NT * DDM];
__device__ __nv_bfloat16  g_ctx_hi[(size_t)NT * DDM];
__device__ __nv_bfloat16  g_ctx_lo[(size_t)NT * DDM];
__device__ __nv_bfloat16  g_wqkv_hi[(size_t)3 * DDM * DDM];
__device__ __nv_bfloat16  g_wqkv_lo[(size_t)3 * DDM * DDM];
__device__ __nv_bfloat16  g_wout_hi[(size_t)DDM * DDM];
__device__ __nv_bfloat16  g_wout_lo[(size_t)DDM * DDM];
__device__ __nv_bfloat16  g_q_hi[(size_t)NT * 64 * HH];
__device__ __nv_bfloat16  g_q_lo[(size_t)NT * 64 * HH];
__device__ __nv_bfloat16  g_k_hi[(size_t)NT * 64 * HH];
__device__ __nv_bfloat16  g_k_lo[(size_t)NT * 64 * HH];
__device__ __nv_bfloat16  g_vT_hi[(size_t)NT * 64 * HH];
__device__ __nv_bfloat16  g_vT_lo[(size_t)NT * 64 * HH];
__device__ float g_cs[LL * 32];
__device__ float g_sn[LL * 32];
__device__ int   g_sid[NT];

// ---------------- streams/events created BEFORE harness checkpoints (static ctor) ----------------
struct GraphStreams {
    cudaStream_t s1 = nullptr, s2 = nullptr;
    cudaEvent_t e0 = nullptr, e1 = nullptr, e2 = nullptr, e3 = nullptr;
    GraphStreams() {
        cudaStreamCreateWithFlags(&s1, cudaStreamNonBlocking);
        cudaStreamCreateWithFlags(&s2, cudaStreamNonBlocking);
        cudaEventCreateWithFlags(&e0, cudaEventDisableTiming);
        cudaEventCreateWithFlags(&e1, cudaEventDisableTiming);
        cudaEventCreateWithFlags(&e2, cudaEventDisableTiming);
        cudaEventCreateWithFlags(&e3, cudaEventDisableTiming);
    }
};
static GraphStreams g_gs;

// ---------------- fused: sequence_id normalize + rope tables ----------------
__global__ void prep_misc_kernel(const void* __restrict__ seqraw) {
    int idx = blockIdx.x * blockDim.x + threadIdx.x;
    if (idx < NT) {
        const int* w = (const int*)seqraw;
        bool is64 = (w[2*1000+1] == 0) && (w[2*1500+1] == 0) && (w[2*2047+1] == 0);
        g_sid[idx] = is64 ? w[2*idx] : w[idx];
    }
    if (idx < LL * 32) {
        int s = idx >> 5, i = idx & 31;
        double ang = (double)s * pow(10000.0, -(double)i / 32.0);
        g_cs[idx] = (float)cos(ang);
        g_sn[idx] = (float)sin(ang);
    }
}

// ---------------- helpers ----------------
__device__ __forceinline__ uint32_t bf16pack(float a, float b) {
    __nv_bfloat16 ha = __float2bfloat16(a), hb = __float2bfloat16(b);
    uint32_t r = ((uint32_t)*(uint16_t*)&hb << 16) | (uint32_t)*(uint16_t*)&ha;
    return r;
}
__device__ __forceinline__ void mma_bf16(float* d, const uint32_t* a, const uint32_t* b) {
    asm volatile(
        "mma.sync.aligned.m16n8k16.row.col.f32.bf16.bf16.f32 "
        "{%0,%1,%2,%3}, {%4,%5,%6,%7}, {%8,%9}, {%0,%1,%2,%3};"
        : "+f"(d[0]), "+f"(d[1]), "+f"(d[2]), "+f"(d[3])
        : "r"(a[0]), "r"(a[1]), "r"(a[2]), "r"(a[3]), "r"(b[0]), "r"(b[1]));
}
__device__ __forceinline__ void ldsm4(uint32_t* r, uint32_t a) {
    asm volatile("ldmatrix.sync.aligned.m8n8.x4.shared.b16 {%0,%1,%2,%3}, [%4];"
        : "=r"(r[0]), "=r"(r[1]), "=r"(r[2]), "=r"(r[3]) : "r"(a));
}
__device__ __forceinline__ void ldsm2(uint32_t* r, uint32_t a) {
    asm volatile("ldmatrix.sync.aligned.m8n8.x2.shared.b16 {%0,%1}, [%2];"
        : "=r"(r[0]), "=r"(r[1]) : "r"(a));
}
__device__ __forceinline__ uint32_t smem_u32(const void* p) {
    uint32_t a;
    asm("{ .reg .u64 t; cvta.to.shared.u64 t, %1; cvt.u32.u64 %0, t; }" : "=r"(a) : "l"(p));
    return a;
}
__device__ __forceinline__ void cp16(uint32_t dst, const void* src) {
    asm volatile("cp.async.cg.shared.global [%0], [%1], 16;" :: "r"(dst), "l"(src));
}
__device__ __forceinline__ void cp_commit() {
    asm volatile("cp.async.commit_group;" ::: "memory");
}
template<int N>
__device__ __forceinline__ void cp_wait() {
    asm volatile("cp.async.wait_group %0;" :: "n"(N) : "memory");
}

// ---------------- weight prep: transpose [K][N] -> [N][K] + bf16 split ----------------
__global__ void __launch_bounds__(256) wprep_kernel(
    const float* __restrict__ w, __nv_bfloat16* __restrict__ thi,
    __nv_bfloat16* __restrict__ tlo, int N) {
    __shared__ float t[32][33];
    int n0 = blockIdx.x * 32, k0 = blockIdx.y * 32;
    int tx = threadIdx.x & 31, ty = threadIdx.x >> 5;
#pragma unroll
    for (int i = 0; i < 4; i++)
        t[ty + 8*i][tx] = w[(size_t)(k0 + ty + 8*i) * N + n0 + tx];
    __syncthreads();
#pragma unroll
    for (int i = 0; i < 4; i++) {
        float v = t[tx][ty + 8*i];
        __nv_bfloat16 h = __float2bfloat16(v);
        __nv_bfloat16 l = __float2bfloat16(v - __bfloat162float(h));
        size_t o = (size_t)(n0 + ty + 8*i) * 1024 + k0 + tx;
        thi[o] = h; tlo[o] = l;
    }
}

// ---------------- input LayerNorm -> bf16 hi/lo split ----------------
__global__ void __launch_bounds__(256) ln_kernel(
    const float* __restrict__ x, const float* __restrict__ w, const float* __restrict__ b) {
    int row = blockIdx.x;
    int tid = threadIdx.x;
    float4 v = ((const float4*)(x + (size_t)row * DDM))[tid];
    float s  = v.x + v.y + v.z + v.w;
    float ss = v.x*v.x + v.y*v.y + v.z*v.z + v.w*v.w;
    __shared__ float rs[8], rss[8];
#pragma unroll
    for (int o = 16; o; o >>= 1) {
        s  += __shfl_xor_sync(0xffffffffu, s,  o);
        ss += __shfl_xor_sync(0xffffffffu, ss, o);
    }
    if ((tid & 31) == 0) { rs[tid >> 5] = s; rss[tid >> 5] = ss; }
    __syncthreads();
    if (tid == 0) {
        float a = 0.f, c = 0.f;
#pragma unroll
        for (int i = 0; i < 8; i++) { a += rs[i]; c += rss[i]; }
        rs[0] = a; rss[0] = c;
    }
    __syncthreads();
    float mean = rs[0] * (1.0f / DDM);
    float var  = rss[0] * (1.0f / DDM) - mean * mean;
    float rstd = rsqrtf(var + 1e-5f);
    float4 wv = ((const float4*)w)[tid];
    float4 bv = ((const float4*)b)[tid];
    float o[4];
    o[0] = (v.x - mean) * rstd * wv.x + bv.x;
    o[1] = (v.y - mean) * rstd * wv.y + bv.y;
    o[2] = (v.z - mean) * rstd * wv.z + bv.z;
    o[3] = (v.w - mean) * rstd * wv.w + bv.w;
    size_t base = (size_t)row * DDM + tid * 4;
    __nv_bfloat16 h[4], l[4];
#pragma unroll
    for (int j = 0; j < 4; j++) {
        h[j] = __float2bfloat16(o[j]);
        l[j] = __float2bfloat16(o[j] - __bfloat162float(h[j]));
    }
    *(uint2*)(g_x_hi + base) = *(uint2*)h;
    *(uint2*)(g_x_lo + base) = *(uint2*)l;
}

// ---------------- tensor GEMM: mma.sync + 2-stage cp.async; V blocks write vT bf16 ----------------
#define SPAD 20
#define ARRW (128 * SPAD)
#define STGW (4 * ARRW)
#define GEMM_SMEM_BYTES (2 * STGW * 4)   // 81920
#define TSPITCH 132
template<int NN, bool WV>
__global__ void __launch_bounds__(256) gemm_mma_kernel(
    const __nv_bfloat16* __restrict__ Ahi, const __nv_bfloat16* __restrict__ Alo,
    const __nv_bfloat16* __restrict__ Bhi, const __nv_bfloat16* __restrict__ Blo,
    float* __restrict__ C, int n_off) {
    extern __shared__ uint32_t sw[];
    const uint32_t sb = smem_u32(sw);
    int tid = threadIdx.x, lane = tid & 31, wid = tid >> 5;
    int m0 = blockIdx.y * 128, n0 = blockIdx.x * 128 + n_off;
    int wm = (wid & 1) * 64, wn = (wid >> 1) * 32;
    int g = lane >> 2, q = lane & 3;
    int lrow = tid >> 2, lu = tid & 3;
    int lr = lane & 7, sel = lane >> 3;

    uint32_t aoff[4], boff[4];
#pragma unroll
    for (int mf = 0; mf < 4; mf++)
        aoff[mf] = (uint32_t)((wm + mf * 16 + (sel & 1) * 8 + lr) * SPAD + (sel >> 1) * 4) * 4;
#pragma unroll
    for (int nf = 0; nf < 4; nf++)
        boff[nf] = (uint32_t)((wn + nf * 8 + lr) * SPAD + (sel & 1) * 4) * 4;

    float acc[4][4][4] = {};

    auto load_chunk = [&](int kc, int st) {
        uint32_t base = sb + (uint32_t)st * (STGW * 4);
#pragma unroll
        for (int h = 0; h < 2; h++) {
            int row = lrow + h * 64;
            uint32_t so = (uint32_t)(row * SPAD + lu * 4) * 4;
            size_t gA = (size_t)(m0 + row) * 1024 + kc * 32 + lu * 8;
            size_t gB = (size_t)(n0 + row) * 1024 + kc * 32 + lu * 8;
            cp16(base + 0 * ARRW * 4 + so, Ahi + gA);
            cp16(base + 1 * ARRW * 4 + so, Alo + gA);
            cp16(base + 2 * ARRW * 4 + so, Bhi + gB);
            cp16(base + 3 * ARRW * 4 + so, Blo + gB);
        }
    };

    load_chunk(0, 0);
    cp_commit();

    for (int kc = 0; kc < 32; kc++) {
        int st = kc & 1;
        if (kc < 31) { load_chunk(kc + 1, st ^ 1); cp_commit(); cp_wait<1>(); }
        else         { cp_wait<0>(); }
        __syncthreads();
        uint32_t stb = sb + (uint32_t)st * (STGW * 4);
        uint32_t bAh = stb, bAl = stb + ARRW * 4, bBh = stb + 2 * ARRW * 4, bBl = stb + 3 * ARRW * 4;
#pragma unroll
        for (int ks = 0; ks < 2; ks++) {
            uint32_t ko = ks * 32;
            uint32_t ah[4][4], al[4][4], bh[4][2], bl[4][2];
#pragma unroll
            for (int mf = 0; mf < 4; mf++) {
                ldsm4(ah[mf], bAh + aoff[mf] + ko);
                ldsm4(al[mf], bAl + aoff[mf] + ko);
            }
#pragma unroll
            for (int nf = 0; nf < 4; nf++) {
                ldsm2(bh[nf], bBh + boff[nf] + ko);
                ldsm2(bl[nf], bBl + boff[nf] + ko);
            }
#pragma unroll
            for (int mf = 0; mf < 4; mf++)
#pragma unroll
                for (int nf = 0; nf < 4; nf++) {
                    mma_bf16(acc[mf][nf], ah[mf], bh[nf]);
                    mma_bf16(acc[mf][nf], ah[mf], bl[nf]);
                    mma_bf16(acc[mf][nf], al[mf], bh[nf]);
                }
        }
        __syncthreads();
    }

    if (WV) {
        float* ts = (float*)sw;
#pragma unroll
        for (int mf = 0; mf < 4; mf++)
#pragma unroll
            for (int nf = 0; nf < 4; nf++)
#pragma unroll
                for (int e = 0; e < 4; e++) {
                    int r = wm + mf * 16 + g + (e >> 1) * 8;
                    int c = wn + nf * 8 + q * 2 + (e & 1);
                    ts[c * TSPITCH + r] = acc[mf][nf][e];
                }
        __syncthreads();
        int b = m0 >> 11, l0v = m0 & (LL - 1);
        int nbase = n0 - 2048;
#pragma unroll
        for (int r8 = 0; r8 < 16; r8++) {
            int row = wid * 16 + r8;
            int nglob = nbase + row;
            int h = nglob >> 6, dh = nglob & 63;
            size_t off = (((size_t)(b * HH + h)) * 64 + dh) * LL + l0v + lane * 4;
            float4 v = *(float4*)&ts[row * TSPITCH + lane * 4];
            __nv_bfloat16 hh[4], llo[4];
            float vv[4] = {v.x, v.y, v.z, v.w};
#pragma unroll
            for (int j = 0; j < 4; j++) {
                hh[j]  = __float2bfloat16(vv[j]);
                llo[j] = __float2bfloat16(vv[j] - __bfloat162float(hh[j]));
            }
            *(uint2*)(g_vT_hi + off) = *(uint2*)hh;
            *(uint2*)(g_vT_lo + off) = *(uint2*)llo;
        }
    } else {
#pragma unroll
        for (int mf = 0; mf < 4; mf++)
#pragma unroll
            for (int nf = 0; nf < 4; nf++) {
                int m = m0 + wm + mf * 16 + g;
                int n = n0 + wn + nf * 8 + q * 2;
                *(float2*)&C[(size_t)m * NN + n]       = make_float2(acc[mf][nf][0], acc[mf][nf][1]);
                *(float2*)&C[(size_t)(m + 8) * NN + n] = make_float2(acc[mf][nf][2], acc[mf][nf][3]);
            }
    }
}

// ---------------- QK LayerNorm + RoPE, q/k passes merged -> head-major bf16 hi/lo ----------------
__global__ void __launch_bounds__(256) qkln_rope_kernel(
    const float* __restrict__ qw, const float* __restrict__ kw) {
    int token = blockIdx.x;
    int tid = threadIdx.x;
    int b = token >> 11, l = token & (LL - 1);
    __shared__ float bufq[DDM], bufk[DDM];
    __shared__ float red[4][8];
    const float* rowq = g_qkv + (size_t)token * 3 * DDM;
    float4 vq = ((const float4*)rowq)[tid];
    float4 vk = ((const float4*)(rowq + DDM))[tid];
    float s0 = vq.x + vq.y + vq.z + vq.w;
    float s1 = vq.x*vq.x + vq.y*vq.y + vq.z*vq.z + vq.w*vq.w;
    float s2 = vk.x + vk.y + vk.z + vk.w;
    float s3 = vk.x*vk.x + vk.y*vk.y + vk.z*vk.z + vk.w*vk.w;
#pragma unroll
    for (int o = 16; o; o >>= 1) {
        s0 += __shfl_xor_sync(0xffffffffu, s0, o);
        s1 += __shfl_xor_sync(0xffffffffu, s1, o);
        s2 += __shfl_xor_sync(0xffffffffu, s2, o);
        s3 += __shfl_xor_sync(0xffffffffu, s3, o);
    }
    if ((tid & 31) == 0) {
        int w = tid >> 5;
        red[0][w] = s0; red[1][w] = s1; red[2][w] = s2; red[3][w] = s3;
    }
    __syncthreads();
    if (tid < 4) {
        float a = 0.f;
#pragma unroll
        for (int i = 0; i < 8; i++) a += red[tid][i];
        red[tid][0] = a;
    }
    __syncthreads();
    float meanq = red[0][0] * (1.0f / DDM);
    float rstdq = rsqrtf(red[1][0] * (1.0f / DDM) - meanq * meanq + 1e-5f);
    float meank = red[2][0] * (1.0f / DDM);
    float rstdk = rsqrtf(red[3][0] * (1.0f / DDM) - meank * meank + 1e-5f);
    float4 wq = ((const float4*)qw)[tid];
    float4 wk = ((const float4*)kw)[tid];
    int c0 = tid * 4;
    bufq[c0 + 0] = (vq.x - meanq) * rstdq * wq.x;
    bufq[c0 + 1] = (vq.y - meanq) * rstdq * wq.y;
    bufq[c0 + 2] = (vq.z - meanq) * rstdq * wq.z;
    bufq[c0 + 3] = (vq.w - meanq) * rstdq * wq.w;
    bufk[c0 + 0] = (vk.x - meank) * rstdk * wk.x;
    bufk[c0 + 1] = (vk.y - meank) * rstdk * wk.y;
    bufk[c0 + 2] = (vk.z - meank) * rstdk * wk.z;
    bufk[c0 + 3] = (vk.w - meank) * rstdk * wk.w;
    __syncthreads();
    __nv_bfloat16 qh[4], ql[4], kh[4], kl[4];
#pragma unroll
    for (int j = 0; j < 4; j++) {
        int c = c0 + j;
        int d = c & 63;
        int i2 = d & 31;
        float cs = g_cs[l * 32 + i2];
        float sn = g_sn[l * 32 + i2];
        float rq = (d < 32) ? -bufq[c + 32] : bufq[c - 32];
        float rk = (d < 32) ? -bufk[c + 32] : bufk[c - 32];
        float oq = bufq[c] * cs + rq * sn;
        float ok = bufk[c] * cs + rk * sn;
        qh[j] = __float2bfloat16(oq);
        ql[j] = __float2bfloat16(oq - __bfloat162float(qh[j]));
        kh[j] = __float2bfloat16(ok);
        kl[j] = __float2bfloat16(ok - __bfloat162float(kh[j]));
    }
    int h = c0 >> 6;
    size_t off = (((size_t)b * HH + h) * LL + l) * 64 + (c0 & 63);
    *(uint2*)(g_q_hi + off) = *(uint2*)qh;
    *(uint2*)(g_q_lo + off) = *(uint2*)ql;
    *(uint2*)(g_k_hi + off) = *(uint2*)kh;
    *(uint2*)(g_k_lo + off) = *(uint2*)kl;
}

// ---------------- tensorized flash attention, 64x64 tiles, active k-range, reg prefetch ----------------
#define APAD 36
struct AttnSmem {
    uint32_t Qh[64*APAD], Ql[64*APAD];
    uint32_t Kh[64*APAD], Kl[64*APAD];
    uint32_t Vh[64*APAD], Vl[64*APAD];   // V^T tiles: [dh][l]
    uint32_t Ph[64*APAD], Pl[64*APAD];
    float Ss[64][65];
    float mrow[64], lrow[64], alpha[64];
    int   sidq[64], sidk[64];
    int   ktlo, kthi;
};

__global__ void __launch_bounds__(256) attn_kernel() {
    extern __shared__ char smem_raw[];
    AttnSmem& sm = *(AttnSmem*)smem_raw;
    int tid = threadIdx.x, lane = tid & 31, wid = tid >> 5;
    int wm = (wid & 1) * 32, wn = (wid >> 1) * 16;
    int g = lane >> 2, q = lane & 3;
    int lr = lane & 7, sel = lane >> 3;
    int q0 = blockIdx.x * 64;
    int bh = blockIdx.y;
    int b = bh >> 4;

    uint32_t aoffA[2], boffB[2];
#pragma unroll
    for (int mf = 0; mf < 2; mf++)
        aoffA[mf] = (uint32_t)((wm + mf * 16 + (sel & 1) * 8 + lr) * APAD + (sel >> 1) * 4) * 4;
#pragma unroll
    for (int nf = 0; nf < 2; nf++)
        boffB[nf] = (uint32_t)((wn + nf * 8 + lr) * APAD + (sel & 1) * 4) * 4;

    const uint32_t uQh = smem_u32(sm.Qh), uQl = smem_u32(sm.Ql);
    const uint32_t uKh = smem_u32(sm.Kh), uKl = smem_u32(sm.Kl);
    const uint32_t uVh = smem_u32(sm.Vh), uVl = smem_u32(sm.Vl);
    const uint32_t uPh = smem_u32(sm.Ph), uPl = smem_u32(sm.Pl);

    auto load_tile = [&](uint32_t* dst, const __nv_bfloat16* src, int rstride) {
#pragma unroll
        for (int i = 0; i < 2; i++) {
            int u = tid + i * 256;
            int row = u >> 3, wq = (u & 7) * 4;
            uint4 v = *(const uint4*)(src + (size_t)row * rstride + wq * 2);
            *(uint4*)&dst[row * APAD + wq] = v;
        }
    };

    uint4 pf[8];
    int sid_next = 0;
    auto prefetch = [&](int kt) {
        const __nv_bfloat16* s0 = g_k_hi  + ((size_t)bh * LL + kt * 64) * 64;
        const __nv_bfloat16* s1 = g_k_lo  + ((size_t)bh * LL + kt * 64) * 64;
        const __nv_bfloat16* s2 = g_vT_hi + (size_t)bh * 64 * LL + kt * 64;
        const __nv_bfloat16* s3 = g_vT_lo + (size_t)bh * 64 * LL + kt * 64;
#pragma unroll
        for (int i = 0; i < 2; i++) {
            int u = tid + i * 256;
            int row = u >> 3, wq = (u & 7) * 4;
            pf[0 * 2 + i] = *(const uint4*)(s0 + (size_t)row * 64 + wq * 2);
            pf[1 * 2 + i] = *(const uint4*)(s1 + (size_t)row * 64 + wq * 2);
            pf[2 * 2 + i] = *(const uint4*)(s2 + (size_t)row * LL + wq * 2);
            pf[3 * 2 + i] = *(const uint4*)(s3 + (size_t)row * LL + wq * 2);
        }
        if (tid < 64) sid_next = g_sid[b * LL + kt * 64 + tid];
    };
    auto commit = [&]() {
#pragma unroll
        for (int i = 0; i < 2; i++) {
            int u = tid + i * 256;
            int row = u >> 3, wq = (u & 7) * 4;
            *(uint4*)&sm.Kh[row * APAD + wq] = pf[0 * 2 + i];
            *(uint4*)&sm.Kl[row * APAD + wq] = pf[1 * 2 + i];
            *(uint4*)&sm.Vh[row * APAD + wq] = pf[2 * 2 + i];
            *(uint4*)&sm.Vl[row * APAD + wq] = pf[3 * 2 + i];
        }
        if (tid < 64) sm.sidk[tid] = sid_next;
    };

    load_tile(sm.Qh, g_q_hi + ((size_t)bh * LL + q0) * 64, 64);
    load_tile(sm.Ql, g_q_lo + ((size_t)bh * LL + q0) * 64, 64);
    if (tid < 64) {
        sm.sidq[tid] = g_sid[b * LL + q0 + tid];
        sm.mrow[tid] = -INFINITY;
        sm.lrow[tid] = 0.f;
    }
    __syncthreads();

    if (tid < 32) {
        int kmin = g_sid[b * LL + tid * 64];
        int kmax = g_sid[b * LL + tid * 64 + 63];
        bool act = (kmax >= sm.sidq[0]) && (kmin <= sm.sidq[63]);
        uint32_t m = __ballot_sync(0xffffffffu, act);
        if (tid == 0) { sm.ktlo = __ffs(m) - 1; sm.kthi = 31 - __clz(m); }
    }
    __syncthreads();
    int ktlo = sm.ktlo, kthi = sm.kthi;

    float O[2][2][4] = {};

    prefetch(ktlo);
    commit();
    __syncthreads();

    for (int kt = ktlo; kt <= kthi; kt++) {
        if (kt < kthi) prefetch(kt + 1);

        float sacc[2][2][4] = {};
#pragma unroll
        for (int ks = 0; ks < 4; ks++) {
            uint32_t ko = ks * 32;
            uint32_t aH[2][4], aL[2][4], bH[2][2], bL[2][2];
#pragma unroll
            for (int mf = 0; mf < 2; mf++) {
                ldsm4(aH[mf], uQh + aoffA[mf] + ko);
                ldsm4(aL[mf], uQl + aoffA[mf] + ko);
            }
#pragma unroll
            for (int nf = 0; nf < 2; nf++) {
                ldsm2(bH[nf], uKh + boffB[nf] + ko);
                ldsm2(bL[nf], uKl + boffB[nf] + ko);
            }
#pragma unroll
            for (int mf = 0; mf < 2; mf++)
#pragma unroll
                for (int nf = 0; nf < 2; nf++) {
                    mma_bf16(sacc[mf][nf], aH[mf], bH[nf]);
                    mma_bf16(sacc[mf][nf], aH[mf], bL[nf]);
                    mma_bf16(sacc[mf][nf], aL[mf], bH[nf]);
                }
        }
#pragma unroll
        for (int mf = 0; mf < 2; mf++)
#pragma unroll
            for (int nf = 0; nf < 2; nf++) {
                int r = wm + mf * 16 + g, c = wn + nf * 8 + 2 * q;
#pragma unroll
                for (int e = 0; e < 4; e++) {
                    int rr = r + (e >> 1) * 8, cc = c + (e & 1);
                    float sv = sacc[mf][nf][e] * 0.125f;
                    if (sm.sidq[rr] != sm.sidk[cc]) sv = -1e30f;
                    sm.Ss[rr][cc] = sv;
                }
            }
        __syncthreads();

        {
            int r = tid >> 2, sub = tid & 3;
            float mloc = -INFINITY;
#pragma unroll
            for (int c = sub * 16; c < sub * 16 + 16; c++)
                mloc = fmaxf(mloc, sm.Ss[r][c]);
            mloc = fmaxf(mloc, __shfl_xor_sync(0xffffffffu, mloc, 1));
            mloc = fmaxf(mloc, __shfl_xor_sync(0xffffffffu, mloc, 2));
            float mold = sm.mrow[r];
            float mnew = fmaxf(mold, mloc);
            float ls = 0.f;
#pragma unroll
            for (int w = sub * 8; w < sub * 8 + 8; w++) {
                float p0 = __expf(sm.Ss[r][2 * w]     - mnew);
                float p1 = __expf(sm.Ss[r][2 * w + 1] - mnew);
                ls += p0 + p1;
                float h0 = __bfloat162float(__float2bfloat16(p0));
                float h1 = __bfloat162float(__float2bfloat16(p1));
                sm.Ph[r * APAD + w] = bf16pack(h0, h1);
                sm.Pl[r * APAD + w] = bf16pack(p0 - h0, p1 - h1);
            }
            ls += __shfl_xor_sync(0xffffffffu, ls, 1);
            ls += __shfl_xor_sync(0xffffffffu, ls, 2);
            if (sub == 0) {
                float a = __expf(mold - mnew);
                sm.alpha[r] = a;
                sm.lrow[r] = sm.lrow[r] * a + ls;
                sm.mrow[r] = mnew;
            }
        }
        __syncthreads();

#pragma unroll
        for (int mf = 0; mf < 2; mf++) {
            float a0 = sm.alpha[wm + mf * 16 + g];
            float a1 = sm.alpha[wm + mf * 16 + g + 8];
#pragma unroll
            for (int nf = 0; nf < 2; nf++) {
                O[mf][nf][0] *= a0; O[mf][nf][1] *= a0;
                O[mf][nf][2] *= a1; O[mf][nf][3] *= a1;
            }
        }
#pragma unroll
        for (int ks = 0; ks < 4; ks++) {
            uint32_t ko = ks * 32;
            uint32_t aH[2][4], aL[2][4], bH[2][2], bL[2][2];
#pragma unroll
            for (int mf = 0; mf < 2; mf++) {
                ldsm4(aH[mf], uPh + aoffA[mf] + ko);
                ldsm4(aL[mf], uPl + aoffA[mf] + ko);
            }
#pragma unroll
            for (int nf = 0; nf < 2; nf++) {
                ldsm2(bH[nf], uVh + boffB[nf] + ko);
                ldsm2(bL[nf], uVl + boffB[nf] + ko);
            }
#pragma unroll
            for (int mf = 0; mf < 2; mf++)
#pragma unroll
                for (int nf = 0; nf < 2; nf++) {
                    mma_bf16(O[mf][nf], aH[mf], bH[nf]);
                    mma_bf16(O[mf][nf], aH[mf], bL[nf]);
                    mma_bf16(O[mf][nf], aL[mf], bH[nf]);
                }
        }
        __syncthreads();
        if (kt < kthi) {
            commit();
            __syncthreads();
        }
    }

    int h = bh & 15;
#pragma unroll
    for (int mf = 0; mf < 2; mf++)
#pragma unroll
        for (int nf = 0; nf < 2; nf++) {
            int r = wm + mf * 16 + g, c = wn + nf * 8 + 2 * q;
#pragma unroll
            for (int half = 0; half < 2; half++) {
                int rr = r + half * 8;
                float il = 1.0f / sm.lrow[rr];
                float o0 = O[mf][nf][half * 2 + 0] * il;
                float o1 = O[mf][nf][half * 2 + 1] * il;
                float h0 = __bfloat162float(__float2bfloat16(o0));
                float h1 = __bfloat162float(__float2bfloat16(o1));
                size_t off = ((size_t)(b * LL + q0 + rr)) * DDM + h * 64 + c;
                *(uint32_t*)(g_ctx_hi + off) = bf16pack(h0, h1);
                *(uint32_t*)(g_ctx_lo + off) = bf16pack(o0 - h0, o1 - h1);
            }
        }
}

// ---------------- launch: stream-forked graph (r14 structure, wprep_qkv moved to s1) ----------------
extern "C" void kernel_launch(void* const* d_in, const int* in_sizes, int n_in,
                              void* d_out, int out_size) {
    (void)in_sizes; (void)n_in; (void)out_size;
    const float* x      = (const float*)d_in[0];
    const void*  seq    = d_in[1];
    const float* ln_w   = (const float*)d_in[2];
    const float* ln_b   = (const float*)d_in[3];
    const float* w_qkv  = (const float*)d_in[4];
    const float* q_ln_w = (const float*)d_in[5];
    const float* k_ln_w = (const float*)d_in[6];
    const float* w_out  = (const float*)d_in[7];
    float* out = (float*)d_out;

    float* p_qkv;
    __nv_bfloat16 *p_xh, *p_xl, *p_ch, *p_cl, *p_wqh, *p_wql, *p_woh, *p_wol;
    cudaGetSymbolAddress((void**)&p_qkv, g_qkv);
    cudaGetSymbolAddress((void**)&p_xh,  g_x_hi);
    cudaGetSymbolAddress((void**)&p_xl,  g_x_lo);
    cudaGetSymbolAddress((void**)&p_ch,  g_ctx_hi);
    cudaGetSymbolAddress((void**)&p_cl,  g_ctx_lo);
    cudaGetSymbolAddress((void**)&p_wqh, g_wqkv_hi);
    cudaGetSymbolAddress((void**)&p_wql, g_wqkv_lo);
    cudaGetSymbolAddress((void**)&p_woh, g_wout_hi);
    cudaGetSymbolAddress((void**)&p_wol, g_wout_lo);

    cudaFuncSetAttribute((const void*)gemm_mma_kernel<3 * DDM, false>,
                         cudaFuncAttributeMaxDynamicSharedMemorySize, GEMM_SMEM_BYTES);
    cudaFuncSetAttribute((const void*)gemm_mma_kernel<3 * DDM, true>,
                         cudaFuncAttributeMaxDynamicSharedMemorySize, GEMM_SMEM_BYTES);
    cudaFuncSetAttribute((const void*)gemm_mma_kernel<DDM, false>,
                         cudaFuncAttributeMaxDynamicSharedMemorySize, GEMM_SMEM_BYTES);
    int attn_smem = (int)sizeof(AttnSmem);
    cudaFuncSetAttribute(attn_kernel, cudaFuncAttributeMaxDynamicSharedMemorySize, attn_smem);

    // fork: ALL prep work (memory-bound) on s1, concurrent with ln on main
    cudaEventRecord(g_gs.e0, 0);
    cudaStreamWaitEvent(g_gs.s1, g_gs.e0, 0);
    prep_misc_kernel<<<(LL * 32 + 255) / 256, 256, 0, g_gs.s1>>>(seq);
    wprep_kernel<<<dim3(DDM / 32, DDM / 32), 256, 0, g_gs.s1>>>(w_out, p_woh, p_wol, DDM);
    wprep_kernel<<<dim3(3 * DDM / 32, DDM / 32), 256, 0, g_gs.s1>>>(w_qkv, p_wqh, p_wql, 3 * DDM);
    cudaEventRecord(g_gs.e1, g_gs.s1);

    // main: LN (concurrent with s1 prep)
    ln_kernel<<<NT, 256>>>(x, ln_w, ln_b);
    cudaEventRecord(g_gs.e2, 0);

    // V-columns GEMM on s2 (needs ln + weights)
    cudaStreamWaitEvent(g_gs.s2, g_gs.e2, 0);
    cudaStreamWaitEvent(g_gs.s2, g_gs.e1, 0);
    gemm_mma_kernel<3 * DDM, true><<<dim3(8, 64), 256, GEMM_SMEM_BYTES, g_gs.s2>>>(
        p_xh, p_xl, p_wqh, p_wql, p_qkv, 2048);
    cudaEventRecord(g_gs.e3, g_gs.s2);

    // QK-columns GEMM on main stream (needs weights from s1)
    cudaStreamWaitEvent(0, g_gs.e1, 0);
    gemm_mma_kernel<3 * DDM, false><<<dim3(16, 64), 256, GEMM_SMEM_BYTES>>>(
        p_xh, p_xl, p_wqh, p_wql, p_qkv, 0);

    // qkln needs qk GEMM (stream order) + rope tables (e1, already waited)
    qkln_rope_kernel<<<NT, 256>>>(q_ln_w, k_ln_w);

    // attention needs vT (e3) + q/k (stream order) + sid (e1, waited)
    cudaStreamWaitEvent(0, g_gs.e3, 0);
    attn_kernel<<<dim3(LL / 64, BB * HH), 256, attn_smem>>>();

    // out-projection (w_out weights ready via e1 wait on main)
    gemm_mma_kernel<DDM, false><<<dim3(DDM / 128, NT / 128), 256, GEMM_SMEM_BYTES>>>(
        p_ch, p_cl, p_woh, p_wol, out, 0);
}